// round 16
// baseline (speedup 1.0000x reference)
#include <cuda_runtime.h>
#include <cuda_bf16.h>
#include <cstdint>

// CTC loss forward: prep kernel (halo e-table, R11 layout) + 2-warp scan with
// 3-STEP blocks. Table: g_E[b][t][lane*12+j] = e at trellis pos 7*lane-3+j.
// scan: 32 CTAs x 64 threads; wid0 = forward alpha (t=1..m, m%3==0),
// wid1 = backward gamma (t=il-1..m+1; blocks of 3 + <=2 single-step tail),
// meet-in-the-middle. cp.async.bulk 3-slot rings, 15 rows/chunk.
// Per block: one shfl set + rebase + renorm serves THREE trellis steps
// (redundant halo: 11 -> 9 -> 7 positions). Per-lane block floating point.

#define TT 1000
#define BB 32
#define CC 1000
#define SS 100
#define RF 384                 // floats per table row (32 lanes x 12)
#define RB (RF * 4)            // 1536 bytes
#define CHR 15                 // rows per scan chunk (multiple of 3)
#define NSLOT 3
#define CHUNK_F (CHR * RF)     // 5760
#define SCAN_SMEM ((2 * NSLOT * CHUNK_F + 256) * 4 + 32 * 4 + 2 * NSLOT * 8)

#define LOG2E_F 1.4426950408889634f
#define LN2_F 0.6931471805599453f
#define NEGF (-1e30f)
#define EDEAD (-(1 << 28))

__device__ float g_E[BB][TT][RF];      // 49 MB static scratch
__device__ float g_loss[BB];
__device__ int g_done;                 // reset by last scan CTA each run

__device__ __forceinline__ float fast_ex2(float x) {
    float y; asm("ex2.approx.ftz.f32 %0, %1;" : "=f"(y) : "f"(x)); return y;
}
__device__ __forceinline__ float fast_lg2(float x) {
    float y; asm("lg2.approx.f32 %0, %1;" : "=f"(y) : "f"(x)); return y;
}
__device__ __forceinline__ uint32_t s2u(const void* p) {
    return (uint32_t)__cvta_generic_to_shared(p);
}
__device__ __forceinline__ void mbar_init(uint64_t* mb, uint32_t cnt) {
    asm volatile("mbarrier.init.shared.b64 [%0], %1;" :: "r"(s2u(mb)), "r"(cnt) : "memory");
}
__device__ __forceinline__ void mbar_wait(uint64_t* mb, uint32_t parity) {
    asm volatile(
        "{\n\t.reg .pred P;\n\t"
        "WL%=:\n\t"
        "mbarrier.try_wait.parity.acquire.cta.shared::cta.b64 P, [%0], %1, 0x989680;\n\t"
        "@P bra WD%=;\n\t"
        "bra WL%=;\n\t"
        "WD%=:\n\t}"
        :: "r"(s2u(mb)), "r"(parity) : "memory");
}
__device__ __forceinline__ void bulk_in(uint32_t dst, const void* src, uint32_t bytes,
                                        uint64_t* mb) {
    asm volatile("mbarrier.arrive.expect_tx.shared.b64 _, [%0], %1;"
                 :: "r"(s2u(mb)), "r"(bytes) : "memory");
    asm volatile("cp.async.bulk.shared::cta.global.mbarrier::complete_tx::bytes "
                 "[%0], [%1], %2, [%3];"
                 :: "r"(dst), "l"(src), "r"(bytes), "r"(s2u(mb)) : "memory");
}
__device__ __forceinline__ float pow2_clamped(int d) {
    int u = 127 + d; if (u < 0) u = 0;
    return __uint_as_float((unsigned)u << 23);
}
__device__ __forceinline__ float skip_into(const int* __restrict__ tg, int b, int Lv, int p) {
    if (p >= 0 && (p & 1) && p < Lv) {
        int si = (p - 1) >> 1;
        if (si > 0) {
            int c0 = tg[b * SS + si];
            int c1 = tg[b * SS + si - 1];
            return (c0 != 0 && c0 != c1) ? 1.0f : 0.0f;
        }
    }
    return 0.0f;
}

// ---------------- prep: halo e-table (identical to R11) ----------------
__global__ void ctc_prep(const float* __restrict__ logp,
                         const int* __restrict__ targets,
                         const int* __restrict__ target_lens) {
    __shared__ __align__(16) float rows[4][CC];
    const int b = blockIdx.y, t0 = blockIdx.x * 4, tid = threadIdx.x;
    const int Lv = 2 * target_lens[b] + 1;
#pragma unroll
    for (int r = 0; r < 4; r++) {
        const float4* s = (const float4*)(logp + ((long)(t0 + r) * BB + b) * CC);
        for (int i = tid; i < CC / 4; i += 256) ((float4*)rows[r])[i] = s[i];
    }
    __syncthreads();
    for (int o = tid; o < 4 * RF; o += 256) {
        int r = o / RF, q = o - r * RF;
        int lane = q / 12, j = q - lane * 12;
        int l = 7 * lane - 3 + j;
        float v = 0.0f;
        if (l >= 0 && l < Lv) {
            int lbl = (l & 1) ? targets[b * SS + (l >> 1)] : 0;
            v = fast_ex2(rows[r][lbl] * LOG2E_F);
        }
        g_E[b][t0 + r][q] = v;
    }
}

// ---- forward 3-step block ----
__device__ __forceinline__ void ftri(float a[7], int& E,
                                     const float* rA, const float* rB, const float* rC,
                                     const float skF[11], int lane) {
    float4 A0 = ((const float4*)rA)[0], A1 = ((const float4*)rA)[1], A2 = ((const float4*)rA)[2];
    float4 B0 = ((const float4*)rB)[0], B1 = ((const float4*)rB)[1], B2 = ((const float4*)rB)[2];
    float4 C0 = ((const float4*)rC)[0], C1 = ((const float4*)rC)[1], C2 = ((const float4*)rC)[2];
    float fA[12] = {A0.x, A0.y, A0.z, A0.w, A1.x, A1.y, A1.z, A1.w, A2.x, A2.y, A2.z, A2.w};

    // prev lane's fA[6] = e at (p-7)-3+6 = p-4
    float e_m4 = __shfl_up_sync(~0u, fA[6], 1);
    float h1 = __shfl_up_sync(~0u, a[1], 1);
    float h2 = __shfl_up_sync(~0u, a[2], 1);
    float h3 = __shfl_up_sync(~0u, a[3], 1);
    float h4 = __shfl_up_sync(~0u, a[4], 1);
    float h5 = __shfl_up_sync(~0u, a[5], 1);
    float h6 = __shfl_up_sync(~0u, a[6], 1);
    int   Ep = __shfl_up_sync(~0u, E, 1);
    if (lane == 0) { h1 = 0.0f; h2 = 0.0f; h3 = 0.0f; h4 = 0.0f; h5 = 0.0f; h6 = 0.0f; e_m4 = 0.0f; }

    int Em = (E > Ep) ? E : Ep;
    float sa = pow2_clamped(E - Em);
    float sp = pow2_clamped(Ep - Em);
    float X[13];                       // alpha at p-6 .. p+6
    X[0] = h1 * sp; X[1] = h2 * sp; X[2] = h3 * sp;
    X[3] = h4 * sp; X[4] = h5 * sp; X[5] = h6 * sp;
#pragma unroll
    for (int j = 0; j < 7; j++) X[6 + j] = a[j] * sa;

    float eA[11];                      // e_tA at p-4 .. p+6
    eA[0] = e_m4;
#pragma unroll
    for (int i = 1; i < 11; i++) eA[i] = fA[i - 1];

    float bt[11];                      // alpha(tA) at p-4 .. p+6
#pragma unroll
    for (int i = 0; i < 11; i++)
        bt[i] = fmaf(skF[i], X[i], X[i + 2] + X[i + 1]) * eA[i];

    float eB[9] = {B0.y, B0.z, B0.w, B1.x, B1.y, B1.z, B1.w, B2.x, B2.y};  // p-2..p+6
    float gm[9];                       // alpha(tB) at p-2 .. p+6
#pragma unroll
    for (int i = 0; i < 9; i++)
        gm[i] = fmaf(skF[i + 2], bt[i], bt[i + 2] + bt[i + 1]) * eB[i];

    float eC[7] = {C0.w, C1.x, C1.y, C1.z, C1.w, C2.x, C2.y};              // p..p+6
    float n[7];                        // alpha(tC) at p .. p+6
#pragma unroll
    for (int j = 0; j < 7; j++)
        n[j] = fmaf(skF[j + 4], gm[j], gm[j + 2] + gm[j + 1]) * eC[j];

    float mm = fmaxf(fmaxf(fmaxf(n[0], n[1]), fmaxf(n[2], n[3])),
                     fmaxf(fmaxf(n[4], n[5]), n[6]));
    unsigned ub = __float_as_uint(mm) >> 23;
    int shift = 127 - (int)ub;          // ub=0 (dead lane) -> 127, exact
    float f = __uint_as_float((unsigned)(shift + 127) << 23);
    E = Em - shift;
#pragma unroll
    for (int j = 0; j < 7; j++) a[j] = n[j] * f;
}

// ---- backward 3-step block ----
__device__ __forceinline__ void btri(float u[7], int& E,
                                     const float* rA, const float* rB, const float* rC,
                                     const float sBx[11], int lane) {
    float4 A0 = ((const float4*)rA)[0], A1 = ((const float4*)rA)[1], A2 = ((const float4*)rA)[2];
    float4 B0 = ((const float4*)rB)[0], B1 = ((const float4*)rB)[1], B2 = ((const float4*)rB)[2];
    float4 C0 = ((const float4*)rC)[0], C1 = ((const float4*)rC)[1], C2 = ((const float4*)rC)[2];
    float fA[12] = {A0.x, A0.y, A0.z, A0.w, A1.x, A1.y, A1.z, A1.w, A2.x, A2.y, A2.z, A2.w};

    // next lane's fA[5] = e at (p+7)-3+5 = p+9 ; fA[6] -> p+10
    float e9  = __shfl_down_sync(~0u, fA[5], 1);
    float e10 = __shfl_down_sync(~0u, fA[6], 1);
    float q0 = __shfl_down_sync(~0u, u[0], 1);
    float q1 = __shfl_down_sync(~0u, u[1], 1);
    float q2 = __shfl_down_sync(~0u, u[2], 1);
    float q3 = __shfl_down_sync(~0u, u[3], 1);
    float q4 = __shfl_down_sync(~0u, u[4], 1);
    float q5 = __shfl_down_sync(~0u, u[5], 1);
    int   Eq = __shfl_down_sync(~0u, E, 1);
    if (lane == 31) { q0 = 0.0f; q1 = 0.0f; q2 = 0.0f; q3 = 0.0f; q4 = 0.0f; q5 = 0.0f;
                      e9 = 0.0f; e10 = 0.0f; }

    int Em = (E > Eq) ? E : Eq;
    float sa = pow2_clamped(E - Em);
    float sq = pow2_clamped(Eq - Em);
    float X[13];                       // u at p .. p+12
#pragma unroll
    for (int j = 0; j < 7; j++) X[j] = u[j] * sa;
    X[7] = q0 * sq; X[8] = q1 * sq; X[9] = q2 * sq;
    X[10] = q3 * sq; X[11] = q4 * sq; X[12] = q5 * sq;

    float eA[11];                      // e_tA at p .. p+10
#pragma unroll
    for (int i = 0; i < 9; i++) eA[i] = fA[3 + i];
    eA[9] = e9; eA[10] = e10;

    float v[11];                       // gamma(tA) at p .. p+10
#pragma unroll
    for (int i = 0; i < 11; i++)
        v[i] = fmaf(sBx[i], X[i + 2], X[i] + X[i + 1]) * eA[i];

    float eB[9] = {B0.w, B1.x, B1.y, B1.z, B1.w, B2.x, B2.y, B2.z, B2.w};  // p..p+8
    float w[9];                        // gamma(tB) at p .. p+8
#pragma unroll
    for (int i = 0; i < 9; i++)
        w[i] = fmaf(sBx[i], v[i + 2], v[i] + v[i + 1]) * eB[i];

    float eC[7] = {C0.w, C1.x, C1.y, C1.z, C1.w, C2.x, C2.y};              // p..p+6
    float n[7];                        // gamma(tC) at p .. p+6
#pragma unroll
    for (int j = 0; j < 7; j++)
        n[j] = fmaf(sBx[j], w[j + 2], w[j] + w[j + 1]) * eC[j];

    float mm = fmaxf(fmaxf(fmaxf(n[0], n[1]), fmaxf(n[2], n[3])),
                     fmaxf(fmaxf(n[4], n[5]), n[6]));
    unsigned ub = __float_as_uint(mm) >> 23;
    int shift = 127 - (int)ub;
    float f = __uint_as_float((unsigned)(shift + 127) << 23);
    E = Em - shift;
#pragma unroll
    for (int j = 0; j < 7; j++) u[j] = n[j] * f;
}

// ---------------- scan ----------------
__global__ void __launch_bounds__(64, 1)
ctc_scan(const float* __restrict__ logp,
         const int* __restrict__ targets,
         const int* __restrict__ input_lens,
         const int* __restrict__ target_lens,
         float* __restrict__ out) {
    extern __shared__ __align__(16) float dsm[];
    float* ringF = dsm;
    float* ringB = dsm + NSLOT * CHUNK_F;
    float* xu = ringB + NSLOT * CHUNK_F;        // 256
    int* xE = (int*)(xu + 256);                 // 32
    uint64_t* mbF = (uint64_t*)(xE + 32);
    uint64_t* mbB = mbF + NSLOT;

    const int b = blockIdx.x;
    const int tid = threadIdx.x;
    const int wid = tid >> 5;
    const int lane = tid & 31;
    const int p = 7 * lane;

    const int il = input_lens[b];
    const int tl = target_lens[b];
    const int Lv = 2 * tl + 1;
    const int end1 = 2 * tl, end2 = 2 * tl - 1;
    const int m = 3 * (((il - 1) >> 1) / 3);    // forward steps, multiple of 3
    int remB = il - 2 - m; if (remB < 0) remB = 0;
    const int tailB = remB % 3;                 // 0..2 single-step tails
    const int bLo = m + 1 + tailB;              // lowest block-region row
    int cntB = il - 1 - bLo; if (cntB < 0) cntB = 0;   // block rows (mult of 3)
    const bool combine = (il > 1);

    if (tid == 0) {
        for (int q = 0; q < NSLOT; q++) { mbar_init(&mbF[q], 1); mbar_init(&mbB[q], 1); }
        asm volatile("fence.proxy.async.shared::cta;" ::: "memory");
    }
    __syncthreads();

    if (wid == 0) {
        // ================= forward consumer =================
        float skF[11];                           // skip-into(p-4+i)
#pragma unroll
        for (int i = 0; i < 11; i++) skF[i] = skip_into(targets, b, Lv, p - 4 + i);

        float a[7];
#pragma unroll
        for (int j = 0; j < 7; j++) a[j] = 0.0f;
        int E = 0;
        if (lane == 0) {
            const float* row0 = logp + (long)b * CC;
            a[0] = fast_ex2(row0[0] * LOG2E_F);
            if (Lv > 1) a[1] = fast_ex2(row0[targets[b * SS]] * LOG2E_F);
        }

        const int nCh = (m + CHR - 1) / CHR;
#pragma unroll
        for (int c = 0; c < NSLOT; c++) {
            if (lane == 0 && c < nCh) {
                int rows_c = m - CHR * c; if (rows_c > CHR) rows_c = CHR;
                bulk_in(s2u(ringF) + c * (CHUNK_F * 4), &g_E[b][1 + CHR * c][0],
                        rows_c * RB, &mbF[c]);
            }
        }

        for (int c = 0; c < nCh; c++) {
            int slot = c % NSLOT;
            mbar_wait(&mbF[slot], (uint32_t)((c / NSLOT) & 1));
            int rows_c = m - CHR * c; if (rows_c > CHR) rows_c = CHR;
            int blocks = rows_c / 3;
            const float* base = ringF + slot * CHUNK_F + lane * 12;
#pragma unroll 1
            for (int kb = 0; kb < blocks; kb++)
                ftri(a, E, base + (3 * kb) * RF, base + (3 * kb + 1) * RF,
                     base + (3 * kb + 2) * RF, skF, lane);

            int c2 = c + NSLOT;
            if (lane == 0 && c2 < nCh) {
                int rows_n = m - CHR * c2; if (rows_n > CHR) rows_n = CHR;
                bulk_in(s2u(ringF) + slot * (CHUNK_F * 4), &g_E[b][1 + CHR * c2][0],
                        rows_n * RB, &mbF[slot]);
            }
        }

        __syncthreads();   // meet

        float g[7];
        int Egam;
        if (combine) {
            float uu[7];
#pragma unroll
            for (int j = 0; j < 7; j++) uu[j] = xu[lane * 8 + j];
            float u7 = (lane < 31) ? xu[(lane + 1) * 8 + 0] : 0.0f;
            float u8 = (lane < 31) ? xu[(lane + 1) * 8 + 1] : 0.0f;
            int Eb = xE[lane];
            int Ebn = (lane < 31) ? xE[lane + 1] : Eb;
            int Em2 = (Eb > Ebn) ? Eb : Ebn;
            float su = pow2_clamped(Eb - Em2);
            float sn = pow2_clamped(Ebn - Em2);
            u7 *= sn; u8 *= sn;
            float sB[7];
#pragma unroll
            for (int j = 0; j < 7; j++) sB[j] = skip_into(targets, b, Lv, p + j + 2);
#pragma unroll
            for (int j = 0; j < 5; j++)
                g[j] = su * fmaf(sB[j], uu[j + 2], uu[j] + uu[j + 1]);
            g[5] = fmaf(sB[5], u7, su * (uu[5] + uu[6]));
            g[6] = su * uu[6] + fmaf(sB[6], u8, u7);
            Egam = Em2;
        } else {
#pragma unroll
            for (int j = 0; j < 7; j++) {
                int l = p + j;
                g[j] = (l == end1 || l == end2) ? 1.0f : 0.0f;
            }
            Egam = 0;
        }

        float cacc = 0.0f;
#pragma unroll
        for (int j = 0; j < 7; j++) cacc = fmaf(a[j], g[j], cacc);
        int Ec = (cacc > 0.0f) ? (E + Egam) : EDEAD;
#pragma unroll
        for (int o = 16; o > 0; o >>= 1) {
            float co2 = __shfl_xor_sync(~0u, cacc, o);
            int   Eo = __shfl_xor_sync(~0u, Ec, o);
            int   Emx = (Ec > Eo) ? Ec : Eo;
            cacc = cacc * pow2_clamped(Ec - Emx) + co2 * pow2_clamped(Eo - Emx);
            Ec = Emx;
        }
        if (lane == 0) {
            float lv = -(fast_lg2(cacc) + (float)Ec) * LN2_F;
            if (!(lv <= 0.5e30f)) lv = 0.0f;     // zero_infinity (inf/nan)
            g_loss[b] = lv;
            __threadfence();
            int old = atomicAdd(&g_done, 1);
            if (old == BB - 1) {
                float sum = 0.0f;
                for (int i = 0; i < BB; i++) sum += g_loss[i];
                out[0] = sum;
                g_done = 0;                       // reset for next replay
            }
        }
    } else {
        // ================= backward consumer =================
        float sBx[11];                            // skip-into(p+i+2)
#pragma unroll
        for (int i = 0; i < 11; i++) sBx[i] = skip_into(targets, b, Lv, p + i + 2);

        float u[7];
        int E = 0;
#pragma unroll
        for (int j = 0; j < 7; j++) {
            int l = p + j;
            float v = 0.0f;
            if (il >= 2 && (l == end1 || l == end2)) {
                int lbl = (l & 1) ? targets[b * SS + ((l - 1) >> 1)] : 0;
                v = fast_ex2(logp[((long)(il - 1) * BB + b) * CC + lbl] * LOG2E_F);
            }
            u[j] = v;
        }

        const int nCh = (cntB + CHR - 1) / CHR;   // block rows, descending
#pragma unroll
        for (int c = 0; c < NSLOT; c++) {
            if (lane == 0 && c < nCh) {
                int hi = il - 2 - CHR * c;
                int lo = hi - CHR + 1; if (lo < bLo) lo = bLo;
                bulk_in(s2u(ringB) + c * (CHUNK_F * 4), &g_E[b][lo][0],
                        (hi - lo + 1) * RB, &mbB[c]);
            }
        }

        for (int c = 0; c < nCh; c++) {
            int slot = c % NSLOT;
            mbar_wait(&mbB[slot], (uint32_t)((c / NSLOT) & 1));
            int hi = il - 2 - CHR * c;
            int lo = hi - CHR + 1; if (lo < bLo) lo = bLo;
            int rows_c = hi - lo + 1;
            int blocks = rows_c / 3;
            const float* base = ringB + slot * CHUNK_F + lane * 12;
#pragma unroll 1
            for (int kb = 0; kb < blocks; kb++) {
                int off = rows_c - 1 - 3 * kb;
                btri(u, E, base + off * RF, base + (off - 1) * RF,
                     base + (off - 2) * RF, sBx, lane);
            }

            int c2 = c + NSLOT;
            if (lane == 0 && c2 < nCh) {
                int hi2 = il - 2 - CHR * c2;
                int lo2 = hi2 - CHR + 1; if (lo2 < bLo) lo2 = bLo;
                bulk_in(s2u(ringB) + slot * (CHUNK_F * 4), &g_E[b][lo2][0],
                        (hi2 - lo2 + 1) * RB, &mbB[slot]);
            }
        }

        // up to 2 single-step tails at rows t = m+tailB .. m+1 (descending)
        for (int s = 0; s < tailB; s++) {
            int t = m + tailB - s;
            const float* rowT = logp + ((long)t * BB + b) * CC;
            float e7[7];
            float lpb = __ldg(rowT);
#pragma unroll
            for (int j = 0; j < 7; j++) {
                int l = p + j;
                float lp = NEGF;
                if (l < Lv) lp = (l & 1) ? __ldg(rowT + targets[b * SS + ((l - 1) >> 1)]) : lpb;
                e7[j] = fast_ex2(lp * LOG2E_F);
            }
            float q0 = __shfl_down_sync(~0u, u[0], 1);
            float q1 = __shfl_down_sync(~0u, u[1], 1);
            int   Eq = __shfl_down_sync(~0u, E, 1);
            if (lane == 31) { q0 = 0.0f; q1 = 0.0f; }
            int Em = (E > Eq) ? E : Eq;
            float sa = pow2_clamped(E - Em);
            float sq = pow2_clamped(Eq - Em);
            float X[9];
#pragma unroll
            for (int j = 0; j < 7; j++) X[j] = u[j] * sa;
            X[7] = q0 * sq; X[8] = q1 * sq;
            float n[7];
#pragma unroll
            for (int j = 0; j < 7; j++)
                n[j] = fmaf(sBx[j], X[j + 2], X[j] + X[j + 1]) * e7[j];
            float mm = fmaxf(fmaxf(fmaxf(n[0], n[1]), fmaxf(n[2], n[3])),
                             fmaxf(fmaxf(n[4], n[5]), n[6]));
            unsigned ub = __float_as_uint(mm) >> 23;
            int shift = 127 - (int)ub;
            float f = __uint_as_float((unsigned)(shift + 127) << 23);
            E = Em - shift;
#pragma unroll
            for (int j = 0; j < 7; j++) u[j] = n[j] * f;
        }

        if (!combine) {                          // il == 1
#pragma unroll
            for (int j = 0; j < 7; j++) {
                int l = p + j;
                u[j] = (l == end1 || l == end2) ? 1.0f : 0.0f;
            }
            E = 0;
        }
#pragma unroll
        for (int j = 0; j < 7; j++) xu[lane * 8 + j] = u[j];
        xu[lane * 8 + 7] = 0.0f;
        xE[lane] = E;
        __syncthreads();   // meet
    }
}

extern "C" void kernel_launch(void* const* d_in, const int* in_sizes, int n_in,
                              void* d_out, int out_size) {
    const float* logp        = (const float*)d_in[0];
    const int*   targets     = (const int*)d_in[1];
    const int*   input_lens  = (const int*)d_in[2];
    const int*   target_lens = (const int*)d_in[3];
    float* out = (float*)d_out;

    cudaFuncSetAttribute(ctc_scan, cudaFuncAttributeMaxDynamicSharedMemorySize, SCAN_SMEM);
    dim3 pg(TT / 4, BB);
    ctc_prep<<<pg, 256>>>(logp, targets, target_lens);
    ctc_scan<<<BB, 64, SCAN_SMEM>>>(logp, targets, input_lens, target_lens, out);
}

// round 17
// speedup vs baseline: 1.1805x; 1.1805x over previous
#include <cuda_runtime.h>
#include <cuda_bf16.h>
#include <cstdint>

// CTC loss forward: prep kernel (halo e-table) + pure 2-warp scan kernel.
// prep: per (t,b) row, stage logp row in SMEM, write 12-float/lane halo table
//       g_E[b][t][lane*12+j] = e at trellis position 7*lane-3+j (0 if invalid).
// scan: 32 CTAs x 64 threads; wid0 = forward alpha (t=1..m), wid1 = backward
//       gamma (t=il-1..m+1), meet-in-the-middle; cp.async.bulk 3-slot rings,
//       24 rows/chunk (halves mbar-wait + refill overhead on the serial chain
//       vs CHR=12); 2 steps per iteration (redundant halo), renorm every 2
//       iterations, per-lane block floating point. Last CTA reduces -> out.

#define TT 1000
#define BB 32
#define CC 1000
#define SS 100
#define RF 384                 // floats per table row (32 lanes x 12)
#define RB (RF * 4)            // 1536 bytes
#define CHR 24                 // rows per scan chunk (even)
#define NSLOT 3
#define CHUNK_F (CHR * RF)
#define SCAN_SMEM ((2 * NSLOT * CHUNK_F + 256) * 4 + 32 * 4 + 2 * NSLOT * 8)

#define LOG2E_F 1.4426950408889634f
#define LN2_F 0.6931471805599453f
#define NEGF (-1e30f)
#define EDEAD (-(1 << 28))

__device__ float g_E[BB][TT][RF];      // 49 MB static scratch
__device__ float g_loss[BB];
__device__ int g_done;                 // zero-init; reset by last CTA each run

__device__ __forceinline__ float fast_ex2(float x) {
    float y; asm("ex2.approx.ftz.f32 %0, %1;" : "=f"(y) : "f"(x)); return y;
}
__device__ __forceinline__ float fast_lg2(float x) {
    float y; asm("lg2.approx.f32 %0, %1;" : "=f"(y) : "f"(x)); return y;
}
__device__ __forceinline__ uint32_t s2u(const void* p) {
    return (uint32_t)__cvta_generic_to_shared(p);
}
__device__ __forceinline__ void mbar_init(uint64_t* mb, uint32_t cnt) {
    asm volatile("mbarrier.init.shared.b64 [%0], %1;" :: "r"(s2u(mb)), "r"(cnt) : "memory");
}
__device__ __forceinline__ void mbar_wait(uint64_t* mb, uint32_t parity) {
    asm volatile(
        "{\n\t.reg .pred P;\n\t"
        "WL%=:\n\t"
        "mbarrier.try_wait.parity.acquire.cta.shared::cta.b64 P, [%0], %1, 0x989680;\n\t"
        "@P bra WD%=;\n\t"
        "bra WL%=;\n\t"
        "WD%=:\n\t}"
        :: "r"(s2u(mb)), "r"(parity) : "memory");
}
__device__ __forceinline__ void bulk_in(uint32_t dst, const void* src, uint32_t bytes,
                                        uint64_t* mb) {
    asm volatile("mbarrier.arrive.expect_tx.shared.b64 _, [%0], %1;"
                 :: "r"(s2u(mb)), "r"(bytes) : "memory");
    asm volatile("cp.async.bulk.shared::cta.global.mbarrier::complete_tx::bytes "
                 "[%0], [%1], %2, [%3];"
                 :: "r"(dst), "l"(src), "r"(bytes), "r"(s2u(mb)) : "memory");
}
__device__ __forceinline__ float pow2_clamped(int d) {
    int u = 127 + d; if (u < 0) u = 0;
    return __uint_as_float((unsigned)u << 23);
}
__device__ __forceinline__ float skip_into(const int* __restrict__ tg, int b, int Lv, int p) {
    if ((p & 1) && p < Lv) {
        int si = (p - 1) >> 1;
        if (si > 0) {
            int c0 = tg[b * SS + si];
            int c1 = tg[b * SS + si - 1];
            return (c0 != 0 && c0 != c1) ? 1.0f : 0.0f;
        }
    }
    return 0.0f;
}

// ---------------- prep: halo e-table ----------------
__global__ void ctc_prep(const float* __restrict__ logp,
                         const int* __restrict__ targets,
                         const int* __restrict__ target_lens) {
    __shared__ __align__(16) float rows[4][CC];
    const int b = blockIdx.y, t0 = blockIdx.x * 4, tid = threadIdx.x;
    const int Lv = 2 * target_lens[b] + 1;
#pragma unroll
    for (int r = 0; r < 4; r++) {
        const float4* s = (const float4*)(logp + ((long)(t0 + r) * BB + b) * CC);
        for (int i = tid; i < CC / 4; i += 256) ((float4*)rows[r])[i] = s[i];
    }
    __syncthreads();
    for (int o = tid; o < 4 * RF; o += 256) {
        int r = o / RF, q = o - r * RF;
        int lane = q / 12, j = q - lane * 12;
        int l = 7 * lane - 3 + j;
        float v = 0.0f;
        if (l >= 0 && l < Lv) {
            int lbl = (l & 1) ? targets[b * SS + (l >> 1)] : 0;
            v = fast_ex2(rows[r][lbl] * LOG2E_F);
        }
        g_E[b][t0 + r][q] = v;
    }
}

// ---- forward pair body (2 time steps); RN: renormalize mantissas ----
template <bool RN>
__device__ __forceinline__ void fpair(float a[7], int& E,
                                      const float* rowA, const float* rowB,
                                      const float skA[9], int lane) {
    const float4* pA = (const float4*)rowA;
    const float4* pB = (const float4*)rowB;
    float4 A0 = pA[0], A1 = pA[1], A2 = pA[2];
    float4 B0 = pB[0], B1 = pB[1], B2 = pB[2];
    float eA[9] = {A0.y, A0.z, A0.w, A1.x, A1.y, A1.z, A1.w, A2.x, A2.y};
    float eB[7] = {B0.w, B1.x, B1.y, B1.z, B1.w, B2.x, B2.y};

    float h3 = __shfl_up_sync(~0u, a[3], 1);
    float h4 = __shfl_up_sync(~0u, a[4], 1);
    float h5 = __shfl_up_sync(~0u, a[5], 1);
    float h6 = __shfl_up_sync(~0u, a[6], 1);
    int   Ep = __shfl_up_sync(~0u, E, 1);
    if (lane == 0) { h3 = 0.0f; h4 = 0.0f; h5 = 0.0f; h6 = 0.0f; }

    int Em = (E > Ep) ? E : Ep;
    float sa = pow2_clamped(E - Em);
    float sp = pow2_clamped(Ep - Em);
    float X[11];                     // alpha at p-4 .. p+6
    X[0] = h3 * sp; X[1] = h4 * sp; X[2] = h5 * sp; X[3] = h6 * sp;
#pragma unroll
    for (int j = 0; j < 7; j++) X[4 + j] = a[j] * sa;

    float bt[9];                     // alpha' at p-2 .. p+6
#pragma unroll
    for (int i = 0; i < 9; i++)
        bt[i] = fmaf(skA[i], X[i], X[i + 2] + X[i + 1]) * eA[i];
    float n[7];                      // alpha'' at p .. p+6
#pragma unroll
    for (int j = 0; j < 7; j++)
        n[j] = fmaf(skA[j + 2], bt[j], bt[j + 2] + bt[j + 1]) * eB[j];

    if (RN) {
        float mm = fmaxf(fmaxf(fmaxf(n[0], n[1]), fmaxf(n[2], n[3])),
                         fmaxf(fmaxf(n[4], n[5]), n[6]));
        unsigned ub = __float_as_uint(mm) >> 23;
        int shift = 127 - (int)ub;          // ub=0 (dead lane) -> 127, exact
        float f = __uint_as_float((unsigned)(shift + 127) << 23);
        E = Em - shift;
#pragma unroll
        for (int j = 0; j < 7; j++) a[j] = n[j] * f;
    } else {
        E = Em;
#pragma unroll
        for (int j = 0; j < 7; j++) a[j] = n[j];
    }
}

// ---- backward pair body ----
template <bool RN>
__device__ __forceinline__ void bpair(float u[7], int& E,
                                      const float* rowA, const float* rowB,
                                      const float sB9[9], int lane) {
    const float4* pA = (const float4*)rowA;
    const float4* pB = (const float4*)rowB;
    float4 A0 = pA[0], A1 = pA[1], A2 = pA[2];
    float4 B0 = pB[0], B1 = pB[1], B2 = pB[2];
    float eA[9] = {A0.w, A1.x, A1.y, A1.z, A1.w, A2.x, A2.y, A2.z, A2.w};
    float eB[7] = {B0.w, B1.x, B1.y, B1.z, B1.w, B2.x, B2.y};

    float q0 = __shfl_down_sync(~0u, u[0], 1);
    float q1 = __shfl_down_sync(~0u, u[1], 1);
    float q2 = __shfl_down_sync(~0u, u[2], 1);
    float q3 = __shfl_down_sync(~0u, u[3], 1);
    int   Eq = __shfl_down_sync(~0u, E, 1);
    if (lane == 31) { q0 = 0.0f; q1 = 0.0f; q2 = 0.0f; q3 = 0.0f; }

    int Em = (E > Eq) ? E : Eq;
    float sa = pow2_clamped(E - Em);
    float sq = pow2_clamped(Eq - Em);
    float X[11];                     // u at p .. p+10
#pragma unroll
    for (int j = 0; j < 7; j++) X[j] = u[j] * sa;
    X[7] = q0 * sq; X[8] = q1 * sq; X[9] = q2 * sq; X[10] = q3 * sq;

    float v[9];                      // gamma_tA at p .. p+8
#pragma unroll
    for (int i = 0; i < 9; i++)
        v[i] = fmaf(sB9[i], X[i + 2], X[i] + X[i + 1]) * eA[i];
    float n[7];
#pragma unroll
    for (int j = 0; j < 7; j++)
        n[j] = fmaf(sB9[j], v[j + 2], v[j] + v[j + 1]) * eB[j];

    if (RN) {
        float mm = fmaxf(fmaxf(fmaxf(n[0], n[1]), fmaxf(n[2], n[3])),
                         fmaxf(fmaxf(n[4], n[5]), n[6]));
        unsigned ub = __float_as_uint(mm) >> 23;
        int shift = 127 - (int)ub;
        float f = __uint_as_float((unsigned)(shift + 127) << 23);
        E = Em - shift;
#pragma unroll
        for (int j = 0; j < 7; j++) u[j] = n[j] * f;
    } else {
        E = Em;
#pragma unroll
        for (int j = 0; j < 7; j++) u[j] = n[j];
    }
}

// ---------------- scan ----------------
__global__ void __launch_bounds__(64, 1)
ctc_scan(const float* __restrict__ logp,
         const int* __restrict__ targets,
         const int* __restrict__ input_lens,
         const int* __restrict__ target_lens,
         float* __restrict__ out) {
    extern __shared__ __align__(16) float dsm[];
    float* ringF = dsm;
    float* ringB = dsm + NSLOT * CHUNK_F;
    float* xu = ringB + NSLOT * CHUNK_F;        // 256
    int* xE = (int*)(xu + 256);                 // 32
    uint64_t* mbF = (uint64_t*)(xE + 32);
    uint64_t* mbB = mbF + NSLOT;

    const int b = blockIdx.x;
    const int tid = threadIdx.x;
    const int wid = tid >> 5;
    const int lane = tid & 31;
    const int p = 7 * lane;

    const int il = input_lens[b];
    const int tl = target_lens[b];
    const int Lv = 2 * tl + 1;
    const int end1 = 2 * tl, end2 = 2 * tl - 1;
    const int m = ((il - 1) >> 1) & ~1;         // even forward step count
    int remB = il - 2 - m; if (remB < 0) remB = 0;
    const int tailB = remB & 1;
    const int bLo = m + 1 + tailB;              // lowest chunked backward row
    int cntB = il - 1 - bLo; if (cntB < 0) cntB = 0;
    const bool combine = (il > 1);

    if (tid == 0) {
        for (int q = 0; q < NSLOT; q++) { mbar_init(&mbF[q], 1); mbar_init(&mbB[q], 1); }
        asm volatile("fence.proxy.async.shared::cta;" ::: "memory");
    }
    __syncthreads();

    if (wid == 0) {
        // ================= forward consumer =================
        float skA[9];                            // skip-into(p-2+i)
#pragma unroll
        for (int i = 0; i < 9; i++) skA[i] = skip_into(targets, b, Lv, p - 2 + i);

        float a[7];
#pragma unroll
        for (int j = 0; j < 7; j++) a[j] = 0.0f;
        int E = 0;
        if (lane == 0) {
            const float* row0 = logp + (long)b * CC;
            a[0] = fast_ex2(row0[0] * LOG2E_F);
            if (Lv > 1) a[1] = fast_ex2(row0[targets[b * SS]] * LOG2E_F);
        }

        const int nCh = (m + CHR - 1) / CHR;     // rows t=1..m
#pragma unroll
        for (int c = 0; c < NSLOT; c++) {
            if (lane == 0 && c < nCh) {
                int rows_c = m - CHR * c; if (rows_c > CHR) rows_c = CHR;
                bulk_in(s2u(ringF) + c * (CHUNK_F * 4), &g_E[b][1 + CHR * c][0],
                        rows_c * RB, &mbF[c]);
            }
        }

        for (int c = 0; c < nCh; c++) {
            int slot = c % NSLOT;
            mbar_wait(&mbF[slot], (uint32_t)((c / NSLOT) & 1));
            int rows_c = m - CHR * c; if (rows_c > CHR) rows_c = CHR;
            int pairs = rows_c >> 1;
            const float* base = ringF + slot * CHUNK_F + lane * 12;
            int q = 0;
            for (; q + 2 <= pairs; q += 2) {
                fpair<false>(a, E, base + (2 * q) * RF, base + (2 * q + 1) * RF, skA, lane);
                fpair<true >(a, E, base + (2 * q + 2) * RF, base + (2 * q + 3) * RF, skA, lane);
            }
            if (q < pairs)
                fpair<true>(a, E, base + (2 * q) * RF, base + (2 * q + 1) * RF, skA, lane);

            int c2 = c + NSLOT;
            if (lane == 0 && c2 < nCh) {
                int rows_n = m - CHR * c2; if (rows_n > CHR) rows_n = CHR;
                bulk_in(s2u(ringF) + slot * (CHUNK_F * 4), &g_E[b][1 + CHR * c2][0],
                        rows_n * RB, &mbF[slot]);
            }
        }

        __syncthreads();   // meet

        float g[7];
        int Egam;
        if (combine) {
            float uu[7];
#pragma unroll
            for (int j = 0; j < 7; j++) uu[j] = xu[lane * 8 + j];
            float u7 = (lane < 31) ? xu[(lane + 1) * 8 + 0] : 0.0f;
            float u8 = (lane < 31) ? xu[(lane + 1) * 8 + 1] : 0.0f;
            int Eb = xE[lane];
            int Ebn = (lane < 31) ? xE[lane + 1] : Eb;
            int Em2 = (Eb > Ebn) ? Eb : Ebn;
            float su = pow2_clamped(Eb - Em2);
            float sn = pow2_clamped(Ebn - Em2);
            u7 *= sn; u8 *= sn;
            float sB[7];
#pragma unroll
            for (int j = 0; j < 7; j++) sB[j] = skip_into(targets, b, Lv, p + j + 2);
#pragma unroll
            for (int j = 0; j < 5; j++)
                g[j] = su * fmaf(sB[j], uu[j + 2], uu[j] + uu[j + 1]);
            g[5] = fmaf(sB[5], u7, su * (uu[5] + uu[6]));
            g[6] = su * uu[6] + fmaf(sB[6], u8, u7);
            Egam = Em2;
        } else {
#pragma unroll
            for (int j = 0; j < 7; j++) {
                int l = p + j;
                g[j] = (l == end1 || l == end2) ? 1.0f : 0.0f;
            }
            Egam = 0;
        }

        float cacc = 0.0f;
#pragma unroll
        for (int j = 0; j < 7; j++) cacc = fmaf(a[j], g[j], cacc);
        int Ec = (cacc > 0.0f) ? (E + Egam) : EDEAD;
#pragma unroll
        for (int o = 16; o > 0; o >>= 1) {
            float co2 = __shfl_xor_sync(~0u, cacc, o);
            int   Eo = __shfl_xor_sync(~0u, Ec, o);
            int   Emx = (Ec > Eo) ? Ec : Eo;
            cacc = cacc * pow2_clamped(Ec - Emx) + co2 * pow2_clamped(Eo - Emx);
            Ec = Emx;
        }
        if (lane == 0) {
            float lv = -(fast_lg2(cacc) + (float)Ec) * LN2_F;
            if (!(lv <= 0.5e30f)) lv = 0.0f;     // zero_infinity (inf/nan)
            g_loss[b] = lv;
            // last-CTA reduction (deterministic: fixed index-order sum)
            __threadfence();
            int old = atomicAdd(&g_done, 1);
            if (old == BB - 1) {
                float sum = 0.0f;
                for (int i = 0; i < BB; i++) sum += g_loss[i];
                out[0] = sum;
                g_done = 0;                       // reset for next graph replay
            }
        }
    } else {
        // ================= backward consumer =================
        float sB9[9];                            // skip-into(p+i+2)
#pragma unroll
        for (int i = 0; i < 9; i++) sB9[i] = skip_into(targets, b, Lv, p + i + 2);

        float u[7];
        int E = 0;
#pragma unroll
        for (int j = 0; j < 7; j++) {
            int l = p + j;
            float v = 0.0f;
            if (il >= 2 && (l == end1 || l == end2)) {
                int lbl = (l & 1) ? targets[b * SS + ((l - 1) >> 1)] : 0;
                v = fast_ex2(logp[((long)(il - 1) * BB + b) * CC + lbl] * LOG2E_F);
            }
            u[j] = v;
        }

        const int nCh = (cntB + CHR - 1) / CHR;  // rows bLo..il-2, descending
#pragma unroll
        for (int c = 0; c < NSLOT; c++) {
            if (lane == 0 && c < nCh) {
                int hi = il - 2 - CHR * c;
                int lo = hi - CHR + 1; if (lo < bLo) lo = bLo;
                bulk_in(s2u(ringB) + c * (CHUNK_F * 4), &g_E[b][lo][0],
                        (hi - lo + 1) * RB, &mbB[c]);
            }
        }

        for (int c = 0; c < nCh; c++) {
            int slot = c % NSLOT;
            mbar_wait(&mbB[slot], (uint32_t)((c / NSLOT) & 1));
            int hi = il - 2 - CHR * c;
            int lo = hi - CHR + 1; if (lo < bLo) lo = bLo;
            int rows_c = hi - lo + 1;
            int pairs = rows_c >> 1;
            const float* base = ringB + slot * CHUNK_F + lane * 12;
            int q = 0;
            for (; q + 2 <= pairs; q += 2) {
                bpair<false>(u, E, base + (rows_c - 1 - 2 * q) * RF,
                             base + (rows_c - 2 - 2 * q) * RF, sB9, lane);
                bpair<true >(u, E, base + (rows_c - 3 - 2 * q) * RF,
                             base + (rows_c - 4 - 2 * q) * RF, sB9, lane);
            }
            if (q < pairs)
                bpair<true>(u, E, base + (rows_c - 1 - 2 * q) * RF,
                            base + (rows_c - 2 - 2 * q) * RF, sB9, lane);

            int c2 = c + NSLOT;
            if (lane == 0 && c2 < nCh) {
                int hi2 = il - 2 - CHR * c2;
                int lo2 = hi2 - CHR + 1; if (lo2 < bLo) lo2 = bLo;
                bulk_in(s2u(ringB) + slot * (CHUNK_F * 4), &g_E[b][lo2][0],
                        (hi2 - lo2 + 1) * RB, &mbB[slot]);
            }
        }

        if (tailB) {
            // one leftover backward step at t = m+1
            const float* rowT = logp + ((long)(m + 1) * BB + b) * CC;
            float e7[7];
            float lpb = __ldg(rowT);
#pragma unroll
            for (int j = 0; j < 7; j++) {
                int l = p + j;
                float lp = NEGF;
                if (l < Lv) lp = (l & 1) ? __ldg(rowT + targets[b * SS + ((l - 1) >> 1)]) : lpb;
                e7[j] = fast_ex2(lp * LOG2E_F);
            }
            float q0 = __shfl_down_sync(~0u, u[0], 1);
            float q1 = __shfl_down_sync(~0u, u[1], 1);
            int   Eq = __shfl_down_sync(~0u, E, 1);
            if (lane == 31) { q0 = 0.0f; q1 = 0.0f; }
            int Em = (E > Eq) ? E : Eq;
            float sa = pow2_clamped(E - Em);
            float sq = pow2_clamped(Eq - Em);
            float X[9];
#pragma unroll
            for (int j = 0; j < 7; j++) X[j] = u[j] * sa;
            X[7] = q0 * sq; X[8] = q1 * sq;
            float n[7];
#pragma unroll
            for (int j = 0; j < 7; j++)
                n[j] = fmaf(sB9[j], X[j + 2], X[j] + X[j + 1]) * e7[j];
            float mm = fmaxf(fmaxf(fmaxf(n[0], n[1]), fmaxf(n[2], n[3])),
                             fmaxf(fmaxf(n[4], n[5]), n[6]));
            unsigned ub = __float_as_uint(mm) >> 23;
            int shift = 127 - (int)ub;
            float f = __uint_as_float((unsigned)(shift + 127) << 23);
            E = Em - shift;
#pragma unroll
            for (int j = 0; j < 7; j++) u[j] = n[j] * f;
        }

        if (!combine) {                          // il == 1
#pragma unroll
            for (int j = 0; j < 7; j++) {
                int l = p + j;
                u[j] = (l == end1 || l == end2) ? 1.0f : 0.0f;
            }
            E = 0;
        }
#pragma unroll
        for (int j = 0; j < 7; j++) xu[lane * 8 + j] = u[j];
        xu[lane * 8 + 7] = 0.0f;
        xE[lane] = E;
        __syncthreads();   // meet
    }
}

extern "C" void kernel_launch(void* const* d_in, const int* in_sizes, int n_in,
                              void* d_out, int out_size) {
    const float* logp        = (const float*)d_in[0];
    const int*   targets     = (const int*)d_in[1];
    const int*   input_lens  = (const int*)d_in[2];
    const int*   target_lens = (const int*)d_in[3];
    float* out = (float*)d_out;

    cudaFuncSetAttribute(ctc_scan, cudaFuncAttributeMaxDynamicSharedMemorySize, SCAN_SMEM);
    dim3 pg(TT / 4, BB);
    ctc_prep<<<pg, 256>>>(logp, targets, target_lens);
    ctc_scan<<<BB, 64, SCAN_SMEM>>>(logp, targets, input_lens, target_lens, out);
}